// round 3
// baseline (speedup 1.0000x reference)
#include <cuda_runtime.h>
#include <cstdint>

#define NTAG      48
#define START_TAG 46
#define STOP_TAG  47
#define BB        128
#define TT        256
#define RS        50                 // padded row stride (floats) -> conflict-free LDS
#define TILE_ELEMS (NTAG * RS)       // 2400 floats per tile buffer
#define NBUF      4                  // cp.async pipeline depth
#define NTHREADS  384                // 12 warps, 3 per SMSP (balances MUFU)

__device__ float g_partials[BB];

__device__ __forceinline__ void cp_async8(uint32_t dst, const void* src) {
    unsigned long long gsrc;
    asm volatile("cvta.to.global.u64 %0, %1;\n" : "=l"(gsrc) : "l"(src));
    asm volatile("cp.async.ca.shared.global [%0], [%1], 8;\n" :: "r"(dst), "l"(gsrc));
}
__device__ __forceinline__ void cp_commit() {
    asm volatile("cp.async.commit_group;\n" ::: "memory");
}
__device__ __forceinline__ void cp_wait_dyn(int n) {
    switch (n) {
        case 0: asm volatile("cp.async.wait_group 0;\n" ::: "memory"); break;
        case 1: asm volatile("cp.async.wait_group 1;\n" ::: "memory"); break;
        case 2: asm volatile("cp.async.wait_group 2;\n" ::: "memory"); break;
        default: asm volatile("cp.async.wait_group 3;\n" ::: "memory"); break;
    }
}

// Copy one 48x48 f32 tile (rows of 192B) into padded SMEM (row stride 200B).
// 1152 x 8B chunks across 384 threads -> exactly 3 per thread.
__device__ __forceinline__ void load_tile(uint32_t sbase, const float* g, int tid) {
    const int r0   = tid / 24;        // 0..15
    const int off8 = (tid % 24) * 8;  // byte offset within 192B row payload
    #pragma unroll
    for (int it = 0; it < 3; ++it) {
        const int row = r0 + 16 * it;
        cp_async8(sbase + (uint32_t)(row * (RS * 4) + off8),
                  (const char*)g + row * (NTAG * 4) + off8);
    }
}

__global__ void __launch_bounds__(NTHREADS, 1) viterbi_fwd(
    const float* __restrict__ feats,
    const void* __restrict__ targets_raw,
    const void* __restrict__ lengths_raw)
{
    __shared__ __align__(16) float tiles[NBUF][TILE_ELEMS];
    __shared__ float sc[2][NTAG];
    __shared__ int   s_tgt[TT];

    const int b   = blockIdx.x;
    const int tid = threadIdx.x;

    // Runtime dtype probe: lengths are sorted descending in [1,256]. A genuine
    // int64 read of element 0 lands in [1,256]; int32 data misread as int64
    // packs two values (hi word >= 1) and is >= 2^32.
    const long long probe = ((const long long*)lengths_raw)[0];
    const bool is64 = (probe >= 1 && probe <= TT);

    int len = is64 ? (int)((const long long*)lengths_raw)[b]
                   : ((const int*)lengths_raw)[b];
    if (len < 1)  len = 1;
    if (len > TT) len = TT;
    const float* fb = feats + (size_t)b * TT * (NTAG * NTAG);

    uint32_t tbase[NBUF];
    #pragma unroll
    for (int i = 0; i < NBUF; ++i)
        tbase[i] = (uint32_t)__cvta_generic_to_shared(&tiles[i][0]);

    // Stage targets for this batch into SMEM (values < 2304; clamp defensively).
    for (int c = tid; c < TT; c += NTHREADS) {
        int v = is64 ? (int)((const long long*)targets_raw)[(size_t)b * TT + c]
                     : ((const int*)targets_raw)[(size_t)b * TT + c];
        if (v < 0) v = 0;
        if (v >= NTAG * NTAG) v = NTAG * NTAG - 1;
        s_tgt[c] = v;
    }

    // Prologue: prefetch up to NBUF tiles (tile p -> buffer p).
    const int npre = (len < NBUF) ? len : NBUF;
    for (int p = 0; p < npre; ++p) {
        load_tile(tbase[p], fb + (size_t)p * (NTAG * NTAG), tid);
        cp_commit();
    }
    cp_wait_dyn(npre - 1);   // tile 0 resident
    __syncthreads();

    // init scores = features[b, 0, START_TAG, :]
    if (tid < NTAG) sc[0][tid] = tiles[0][START_TAG * RS + tid];
    float gold = 0.0f;
    if (tid == 0) {
        const int tg = s_tgt[0];
        gold = tiles[0][(tg / NTAG) * RS + (tg % NTAG)];
    }
    __syncthreads();   // all init reads of buffer 0 done before it is overwritten

    const int j = tid >> 3;   // destination tag 0..47
    const int s = tid & 7;    // source-tag slice 0..7 (6 rows each)
    int cur = 0;

    for (int t = 1; t < len; ++t) {
        const int nt = t + (NBUF - 1);
        if (nt < len) {
            load_tile(tbase[nt & (NBUF - 1)], fb + (size_t)nt * (NTAG * NTAG), tid);
            cp_commit();
        }
        int pend = len - 1 - t;
        if (pend > NBUF - 1) pend = NBUF - 1;
        cp_wait_dyn(pend);   // tile t resident
        __syncthreads();

        const float* tl = tiles[t & (NBUF - 1)];

        float w[6];
        float m = -3.0e38f;
        #pragma unroll
        for (int k = 0; k < 6; ++k) {
            const int i = s * 6 + k;
            const float v = tl[i * RS + j] + sc[cur][i];
            w[k] = v;
            m = fmaxf(m, v);
        }
        m = fmaxf(m, __shfl_xor_sync(0xffffffffu, m, 1));
        m = fmaxf(m, __shfl_xor_sync(0xffffffffu, m, 2));
        m = fmaxf(m, __shfl_xor_sync(0xffffffffu, m, 4));

        float sum = 0.0f;
        #pragma unroll
        for (int k = 0; k < 6; ++k) sum += __expf(w[k] - m);
        sum += __shfl_xor_sync(0xffffffffu, sum, 1);
        sum += __shfl_xor_sync(0xffffffffu, sum, 2);
        sum += __shfl_xor_sync(0xffffffffu, sum, 4);

        if (s == 0) sc[cur ^ 1][j] = m + __logf(sum);

        if (tid == 0) {
            const int tg = s_tgt[t];
            gold += tl[(tg / NTAG) * RS + (tg % NTAG)];
        }
        __syncthreads();   // sc swap published + tile buffer free for reuse
        cur ^= 1;
    }

    if (tid == 0) g_partials[b] = sc[cur][STOP_TAG] - gold;
}

// Deterministic fixed-order reduction of the 128 per-batch partials.
__global__ void reduce_out(float* __restrict__ out) {
    __shared__ float sh[BB];
    const int t = threadIdx.x;
    sh[t] = g_partials[t];
    __syncthreads();
    #pragma unroll
    for (int st = 64; st > 0; st >>= 1) {
        if (t < st) sh[t] += sh[t + st];
        __syncthreads();
    }
    if (t == 0) out[0] = sh[0];
}

extern "C" void kernel_launch(void* const* d_in, const int* in_sizes, int n_in,
                              void* d_out, int out_size) {
    // Bind inputs by element count, not position: features=B*T*48*48, targets=B*T, lengths=B.
    const float* feats   = nullptr;
    const void*  targets = nullptr;
    const void*  lengths = nullptr;
    for (int i = 0; i < n_in; ++i) {
        if (in_sizes[i] == BB * TT * NTAG * NTAG) feats   = (const float*)d_in[i];
        else if (in_sizes[i] == BB * TT)          targets = d_in[i];
        else if (in_sizes[i] == BB)               lengths = d_in[i];
    }
    viterbi_fwd<<<BB, NTHREADS>>>(feats, targets, lengths);
    reduce_out<<<1, BB>>>((float*)d_out);
}